// round 8
// baseline (speedup 1.0000x reference)
#include <cuda_runtime.h>
#include <math.h>

#define EPS 1e-5f
#define MAX_BK 32768
typedef unsigned long long u64;

// ---- scratch (device globals) ----
__device__ float4 g_sums[MAX_BK];           // per-bin {sum fx, sum fy, sum_i, sum_j}
__device__ float  g_cnt [MAX_BK];
__device__ float  g_x  [(size_t)5  * MAX_BK];   // feature-major token features [5][BK]
__device__ float  g_t2 [(size_t)MAX_BK * 32];   // token-major layer-2 pre-BN [BK][32]
__device__ float  g_xstat[20];              // Sx(5) + upper-tri Sxx(15)
__device__ float  g_st2[64];                // [0:32) sum, [32:64) sumsq layer-2

__device__ __forceinline__ void red_v4(float4* p, float a, float b, float c, float d) {
    asm volatile("red.global.add.v4.f32 [%0], {%1,%2,%3,%4};"
                 :: "l"(p), "f"(a), "f"(b), "f"(c), "f"(d) : "memory");
}
__device__ __forceinline__ void red_f(float* p, float v) {
    asm volatile("red.global.add.f32 [%0], %1;" :: "l"(p), "f"(v) : "memory");
}

// ---- kernel 0: zero accumulators ----
__global__ void zero_k(int bk) {
    int i = blockIdx.x * blockDim.x + threadIdx.x;
    if (i < bk) { g_sums[i] = make_float4(0.f, 0.f, 0.f, 0.f); g_cnt[i] = 0.f; }
    if (i < 20) g_xstat[i] = 0.f;
    if (i < 64) g_st2[i] = 0.f;
}

// ---- pool (fast path): CTA = 4096 pixels, 2 packed u64 smem atomics / pixel ----
// s_ij: [40:64) sum_i, [16:40) sum_j, [0:16) count
// s_xy: lo32 = sum(round(fx*4096)+65536), hi32 = same for fy (4096 px -> < 2^31)
__global__ void pool_priv_k(const int*   __restrict__ labels,
                            const float* __restrict__ fxp,
                            const float* __restrict__ fyp,
                            int P, int h, int K, int cpb) {
    extern __shared__ char sm[];
    u64* s_ij = (u64*)sm;                       // [K]
    u64* s_xy = (u64*)(sm + (size_t)K * 8);     // [K]
    int t = threadIdx.x;
    for (int q = t; q < K; q += 256) { s_ij[q] = 0ull; s_xy[q] = 0ull; }
    __syncthreads();

    int b     = blockIdx.x / cpb;
    int chunk = blockIdx.x - b * cpb;
    int base4 = (b * P + chunk * 4096) >> 2;
#pragma unroll
    for (int it = 0; it < 4; it++) {
        int g4 = base4 + it * 256 + t;
        int4   lb = ((const int4*)  labels)[g4];
        float4 vx = ((const float4*)fxp)[g4];
        float4 vy = ((const float4*)fyp)[g4];
        int p0  = g4 << 2;
        int pin = p0 - b * P;
        int i   = pin / h;
        int j   = pin - i * h;              // h % 4 == 0 -> 4-pack same row
        u64 bi = ((u64)i << 40) | 1ull;
        unsigned ax, ay;
        ax = (unsigned)__float2int_rn(fmaf(vx.x, 4096.f, 65536.f));
        ay = (unsigned)__float2int_rn(fmaf(vy.x, 4096.f, 65536.f));
        atomicAdd(&s_xy[lb.x], ((u64)ay << 32) | ax);
        atomicAdd(&s_ij[lb.x], bi | ((u64)(j + 0) << 16));
        ax = (unsigned)__float2int_rn(fmaf(vx.y, 4096.f, 65536.f));
        ay = (unsigned)__float2int_rn(fmaf(vy.y, 4096.f, 65536.f));
        atomicAdd(&s_xy[lb.y], ((u64)ay << 32) | ax);
        atomicAdd(&s_ij[lb.y], bi | ((u64)(j + 1) << 16));
        ax = (unsigned)__float2int_rn(fmaf(vx.z, 4096.f, 65536.f));
        ay = (unsigned)__float2int_rn(fmaf(vy.z, 4096.f, 65536.f));
        atomicAdd(&s_xy[lb.z], ((u64)ay << 32) | ax);
        atomicAdd(&s_ij[lb.z], bi | ((u64)(j + 2) << 16));
        ax = (unsigned)__float2int_rn(fmaf(vx.w, 4096.f, 65536.f));
        ay = (unsigned)__float2int_rn(fmaf(vy.w, 4096.f, 65536.f));
        atomicAdd(&s_xy[lb.w], ((u64)ay << 32) | ax);
        atomicAdd(&s_ij[lb.w], bi | ((u64)(j + 3) << 16));
    }
    __syncthreads();
    for (int q = t; q < K; q += 256) {
        u64 p = s_ij[q];
        if (p) {
            unsigned c = (unsigned)(p & 0xFFFFull);
            float sj = (float)(unsigned)((p >> 16) & 0xFFFFFFull);
            float si = (float)(unsigned)(p >> 40);
            u64 pxy = s_xy[q];
            long long ix = (long long)(unsigned)(pxy & 0xFFFFFFFFull) - (long long)c * 65536ll;
            long long iy = (long long)(unsigned)(pxy >> 32)           - (long long)c * 65536ll;
            float fxs = (float)ix * (1.f / 4096.f);
            float fys = (float)iy * (1.f / 4096.f);
            red_v4(&g_sums[b * K + q], fxs, fys, si, sj);
            red_f(&g_cnt[b * K + q], (float)c);
        }
    }
}

// ---- pool fallback: direct global REDs ----
__global__ void pool_gl_k(const int*   __restrict__ labels,
                          const float* __restrict__ fxp,
                          const float* __restrict__ fyp,
                          int P, int h, int K, int Np) {
    int p0 = blockIdx.x * blockDim.x + threadIdx.x;
    if (p0 >= Np) return;
    int b   = p0 / P;
    int pin = p0 - b * P;
    int i   = pin / h;
    int j   = pin - i * h;
    int l   = labels[p0];
    red_v4(&g_sums[b * K + l], fxp[p0], fyp[p0], (float)i, (float)j);
    red_f(&g_cnt[b * K + l], 1.f);
}

// ---- stats: per-token x[5] -> g_x (feature-major), accumulate Sx / Sxx ----
__global__ void stats_k(const int* __restrict__ fidx,
                        const int* __restrict__ nfp,
                        int K, int BK, float sx, float sy) {
    int tok  = blockIdx.x * 256 + threadIdx.x;
    int lane = threadIdx.x & 31;
    float v[20];
#pragma unroll
    for (int q = 0; q < 20; q++) v[q] = 0.f;
    if (tok < BK) {
        int nf = nfp ? *nfp : 100;
        float invnf = 1.f / (float)(nf - 1);
        int b = tok / K;
        float x0 = (float)__ldg(&fidx[b]) * invnf;
        float cr = g_cnt[tok];
        float ic = 1.f / fmaxf(cr, 1.f);
        float4 s = g_sums[tok];
        float x1 = s.x * ic, x2 = s.y * ic;
        float x3 = (cr > 0.f) ? fmaf(s.z * ic, sx, -1.f) : 0.f;
        float x4 = (cr > 0.f) ? fmaf(s.w * ic, sy, -1.f) : 0.f;
        g_x[tok]          = x0;
        g_x[BK + tok]     = x1;
        g_x[2 * BK + tok] = x2;
        g_x[3 * BK + tok] = x3;
        g_x[4 * BK + tok] = x4;
        float xv[5] = {x0, x1, x2, x3, x4};
        int ix = 0;
#pragma unroll
        for (int d = 0; d < 5; d++) v[ix++] = xv[d];
#pragma unroll
        for (int d = 0; d < 5; d++)
#pragma unroll
            for (int e = d; e < 5; e++) v[ix++] = xv[d] * xv[e];
    }
#pragma unroll
    for (int q = 0; q < 20; q++) {
#pragma unroll
        for (int off = 16; off; off >>= 1)
            v[q] += __shfl_xor_sync(0xffffffffu, v[q], off);
    }
    if (lane == 0) {
#pragma unroll
        for (int q = 0; q < 20; q++) red_f(&g_xstat[q], v[q]);
    }
}

// ---- fused mlp1+mlp2: thread = (token, 8-output quarter). 65536 threads. ----
__global__ void __launch_bounds__(128) mlp12_k(
        const float* __restrict__ cw,   // [64,5]
        const float* __restrict__ cbp,  // [64]
        const float* __restrict__ g1,
        const float* __restrict__ b1,
        const float* __restrict__ lw,   // [32,64]
        const float* __restrict__ lbp,  // [32]
        int BK, float invN) {
    __shared__ float xs[20];
    __shared__ float cw2p[512];          // folded conv coefs: w0..w4, cb, pad, pad per ch
    __shared__ float wsm[2048];          // lw [32][64]
    __shared__ float lbs[32];
    __shared__ float ssum[32], ssq[32];
    __shared__ float tile[4 * 264];      // per-warp 8 tokens x stride-33 transpose

    int t = threadIdx.x, lane = t & 31, w = t >> 5;
    if (t < 20) xs[t] = g_xstat[t];
    if (t < 32) { lbs[t] = __ldg(&lbp[t]); ssum[t] = 0.f; ssq[t] = 0.f; }
    for (int q = t; q < 2048; q += 128) wsm[q] = __ldg(&lw[q]);
    __syncthreads();
    if (t < 64) {
        int ch = t;
        float wv[5];
#pragma unroll
        for (int d = 0; d < 5; d++) wv[d] = __ldg(&cw[ch * 5 + d]);
        float bv = __ldg(&cbp[ch]);
        float m0 = 0.f;
#pragma unroll
        for (int d = 0; d < 5; d++) m0 = fmaf(wv[d], xs[d] * invN, m0);
        float q2 = 0.f; int ix = 5;
#pragma unroll
        for (int d = 0; d < 5; d++)
#pragma unroll
            for (int e = d; e < 5; e++) {
                float S = xs[ix++] * invN;
                q2 = fmaf((d == e ? 1.f : 2.f) * wv[d] * wv[e], S, q2);
            }
        float var = q2 - m0 * m0;
        float sc  = __ldg(&g1[ch]) * rsqrtf(var + EPS);
        float cbf = fmaf(bv, sc, __ldg(&b1[ch]) - (m0 + bv) * sc);
#pragma unroll
        for (int d = 0; d < 5; d++) cw2p[ch * 8 + d] = wv[d] * sc;
        cw2p[ch * 8 + 5] = cbf;
        cw2p[ch * 8 + 6] = 0.f;
        cw2p[ch * 8 + 7] = 0.f;
    }
    __syncthreads();

    int tok = blockIdx.x * 32 + (t >> 2);
    int qt  = t & 3;                     // which 8-output group
    bool act = tok < BK;
    int tclamp = act ? tok : (BK - 1);
    float x0 = g_x[tclamp];
    float x1 = g_x[BK + tclamp];
    float x2 = g_x[2 * BK + tclamp];
    float x3 = g_x[3 * BK + tclamp];
    float x4 = g_x[4 * BK + tclamp];

    float o[8];
#pragma unroll
    for (int c = 0; c < 8; c++) o[c] = lbs[qt * 8 + c];

    const float4* cw4 = (const float4*)cw2p;
    const float4* w4  = (const float4*)wsm;
#pragma unroll
    for (int chunk = 0; chunk < 4; chunk++) {
        float z[16];
#pragma unroll
        for (int c = 0; c < 16; c++) {
            int ch = chunk * 16 + c;
            float4 a = cw4[ch * 2];
            float4 b = cw4[ch * 2 + 1];
            float v = fmaf(a.x, x0, fmaf(a.y, x1, fmaf(a.z, x2,
                      fmaf(a.w, x3, fmaf(b.x, x4, b.y)))));
            z[c] = fmaxf(v, 0.f);
        }
#pragma unroll
        for (int cc = 0; cc < 8; cc++) {
            int row = (qt * 8 + cc) * 16 + chunk * 4;
#pragma unroll
            for (int q = 0; q < 4; q++) {
                float4 ww = w4[row + q];
                o[cc] = fmaf(z[q*4+0], ww.x, fmaf(z[q*4+1], ww.y,
                        fmaf(z[q*4+2], ww.z, fmaf(z[q*4+3], ww.w, o[cc]))));
            }
        }
    }
    if (!act) {
#pragma unroll
        for (int c = 0; c < 8; c++) o[c] = 0.f;
    }
    if (act) {
        float4* dst = (float4*)&g_t2[(size_t)tok * 32 + qt * 8];
        dst[0] = make_float4(o[0], o[1], o[2], o[3]);
        dst[1] = make_float4(o[4], o[5], o[6], o[7]);
    }

    // BN2 stats: per-warp smem transpose (8 tokens x 32 channels, stride 33)
    float* tw = tile + w * 264;
    int tokin = (t >> 2) & 7;
#pragma unroll
    for (int c = 0; c < 8; c++)
        tw[tokin * 33 + qt * 8 + c] = o[c];
    __syncwarp();
    float s1 = 0.f, s2 = 0.f;
#pragma unroll
    for (int i = 0; i < 8; i++) {
        float v = tw[i * 33 + lane];
        s1 += v; s2 = fmaf(v, v, s2);
    }
    atomicAdd(&ssum[lane], s1);
    atomicAdd(&ssq[lane], s2);
    __syncthreads();
    if (t < 32) { red_f(&g_st2[t], ssum[t]); red_f(&g_st2[32 + t], ssq[t]); }
}

// ---- mlp3: warp per 8 tokens, lane = channel; butterfly norm; coalesced I/O ----
__global__ void mlp3_k(const float* __restrict__ g2,
                       const float* __restrict__ b2,
                       float* __restrict__ out,
                       int BK, float invN) {
    __shared__ float sc[32], sh[32];
    int t = threadIdx.x, lane = t & 31, w = t >> 5;
    if (t < 32) {
        float m   = g_st2[t] * invN;
        float var = g_st2[32 + t] * invN - m * m;
        float s   = g2[t] * rsqrtf(var + EPS);
        sc[t] = s; sh[t] = b2[t] - m * s;
    }
    __syncthreads();
    float scl = sc[lane], shl = sh[lane];
    int tok0 = (blockIdx.x * 8 + w) * 8;
    float v[8];
#pragma unroll
    for (int tt = 0; tt < 8; tt++) {
        int tok = tok0 + tt;
        v[tt] = (tok < BK) ? g_t2[(size_t)tok * 32 + lane] : 0.f;
    }
#pragma unroll
    for (int tt = 0; tt < 8; tt++) {
        float x = fmaxf(fmaf(v[tt], scl, shl), 0.f);
        float n = x * x;
#pragma unroll
        for (int off = 16; off; off >>= 1)
            n += __shfl_xor_sync(0xffffffffu, n, off);
        float inv = 1.f / fmaxf(sqrtf(n), 1e-8f);
        int tok = tok0 + tt;
        if (tok < BK) out[(size_t)tok * 32 + lane] = x * inv;
    }
}

extern "C" void kernel_launch(void* const* d_in, const int* in_sizes, int n_in,
                              void* d_out, int out_size) {
    const int*   labels = (const int*)  d_in[0];
    const float* fx     = (const float*)d_in[1];
    const float* fy     = (const float*)d_in[2];
    const int*   fidx   = (const int*)  d_in[3];
    int wi = 4;
    const int* nfp = nullptr;
    if (n_in >= 14) { nfp = (const int*)d_in[4]; wi = 6; }
    const float* cw = (const float*)d_in[wi + 0];
    const float* cb = (const float*)d_in[wi + 1];
    const float* g1 = (const float*)d_in[wi + 2];
    const float* b1 = (const float*)d_in[wi + 3];
    const float* lw = (const float*)d_in[wi + 4];
    const float* lb = (const float*)d_in[wi + 5];
    const float* g2 = (const float*)d_in[wi + 6];
    const float* b2 = (const float*)d_in[wi + 7];

    int B  = in_sizes[3];
    int Np = in_sizes[0];
    int P  = Np / B;
    int BK = out_size / 32;
    int K  = BK / B;
    int hh = (int)(sqrt((double)P) + 0.5);
    int ww = P / hh;
    float sx = 2.f / (float)(ww - 1);
    float sy = 2.f / (float)(hh - 1);

    zero_k<<<(BK + 255) / 256, 256>>>(BK);

    bool fast = (hh * ww == P) && (hh % 4 == 0) && (P % 4096 == 0) &&
                (K <= 2048) && (hh <= 1024) && (ww <= 1024);
    if (fast) {
        int cpb = P / 4096;
        pool_priv_k<<<B * cpb, 256, (size_t)K * 16>>>(labels, fx, fy, P, hh, K, cpb);
    } else {
        pool_gl_k<<<(Np + 255) / 256, 256>>>(labels, fx, fy, P, hh, K, Np);
    }

    float invN = 1.f / (float)BK;
    stats_k<<<(BK + 255) / 256, 256>>>(fidx, nfp, K, BK, sx, sy);
    mlp12_k<<<(BK + 31) / 32, 128>>>(cw, cb, g1, b1, lw, lb, BK, invN);
    mlp3_k<<<(BK + 63) / 64, 256>>>(g2, b2, (float*)d_out, BK, invN);
}

// round 9
// speedup vs baseline: 1.0339x; 1.0339x over previous
#include <cuda_runtime.h>
#include <math.h>

#define EPS 1e-5f
#define MAX_BK 32768
typedef unsigned long long u64;

// ---- scratch (device globals) ----
__device__ float4 g_sums[MAX_BK];           // per-bin {sum fx, sum fy, sum_i, sum_j}
__device__ float  g_cnt [MAX_BK];
__device__ float  g_x  [(size_t)5  * MAX_BK];   // feature-major token features [5][BK]
__device__ float  g_t2 [(size_t)MAX_BK * 32];   // token-major layer-2 pre-BN [BK][32]
__device__ float  g_xstat[20];              // Sx(5) + upper-tri Sxx(15)
__device__ float  g_st2[64];                // [0:32) sum, [32:64) sumsq layer-2
__device__ unsigned g_bar[2];               // grid barrier counters (reset by pool)

__device__ __forceinline__ void red_v4(float4* p, float a, float b, float c, float d) {
    asm volatile("red.global.add.v4.f32 [%0], {%1,%2,%3,%4};"
                 :: "l"(p), "f"(a), "f"(b), "f"(c), "f"(d) : "memory");
}
__device__ __forceinline__ void red_f(float* p, float v) {
    asm volatile("red.global.add.f32 [%0], %1;" :: "l"(p), "f"(v) : "memory");
}

__device__ __forceinline__ void grid_barrier(int i, unsigned nCTA) {
    __syncthreads();
    if (threadIdx.x == 0) {
        __threadfence();
        atomicAdd(&g_bar[i], 1u);
        while (atomicAdd(&g_bar[i], 0u) < nCTA) __nanosleep(64);
    }
    __syncthreads();
    __threadfence();
}

// ---- pool (fast path): CTA = 4096 pixels, 2 packed u64 smem atomics / pixel ----
// Also resets the small cross-kernel state (safe: kernel boundary before mlp_all).
__global__ void pool_priv_k(const int*   __restrict__ labels,
                            const float* __restrict__ fxp,
                            const float* __restrict__ fyp,
                            int P, int h, int K, int cpb) {
    extern __shared__ char sm[];
    u64* s_ij = (u64*)sm;                       // [K]
    u64* s_xy = (u64*)(sm + (size_t)K * 8);     // [K]
    int t = threadIdx.x;
    if (blockIdx.x == 0) {
        if (t < 20) g_xstat[t] = 0.f;
        if (t < 64) g_st2[t] = 0.f;
        if (t < 2)  g_bar[t] = 0u;
    }
    for (int q = t; q < K; q += 256) { s_ij[q] = 0ull; s_xy[q] = 0ull; }
    __syncthreads();

    int b     = blockIdx.x / cpb;
    int chunk = blockIdx.x - b * cpb;
    int base4 = (b * P + chunk * 4096) >> 2;
#pragma unroll
    for (int it = 0; it < 4; it++) {
        int g4 = base4 + it * 256 + t;
        int4   lb = ((const int4*)  labels)[g4];
        float4 vx = ((const float4*)fxp)[g4];
        float4 vy = ((const float4*)fyp)[g4];
        int p0  = g4 << 2;
        int pin = p0 - b * P;
        int i   = pin / h;
        int j   = pin - i * h;              // h % 4 == 0 -> 4-pack same row
        u64 bi = ((u64)i << 40) | 1ull;
        unsigned ax, ay;
        ax = (unsigned)__float2int_rn(fmaf(vx.x, 4096.f, 65536.f));
        ay = (unsigned)__float2int_rn(fmaf(vy.x, 4096.f, 65536.f));
        atomicAdd(&s_xy[lb.x], ((u64)ay << 32) | ax);
        atomicAdd(&s_ij[lb.x], bi | ((u64)(j + 0) << 16));
        ax = (unsigned)__float2int_rn(fmaf(vx.y, 4096.f, 65536.f));
        ay = (unsigned)__float2int_rn(fmaf(vy.y, 4096.f, 65536.f));
        atomicAdd(&s_xy[lb.y], ((u64)ay << 32) | ax);
        atomicAdd(&s_ij[lb.y], bi | ((u64)(j + 1) << 16));
        ax = (unsigned)__float2int_rn(fmaf(vx.z, 4096.f, 65536.f));
        ay = (unsigned)__float2int_rn(fmaf(vy.z, 4096.f, 65536.f));
        atomicAdd(&s_xy[lb.z], ((u64)ay << 32) | ax);
        atomicAdd(&s_ij[lb.z], bi | ((u64)(j + 2) << 16));
        ax = (unsigned)__float2int_rn(fmaf(vx.w, 4096.f, 65536.f));
        ay = (unsigned)__float2int_rn(fmaf(vy.w, 4096.f, 65536.f));
        atomicAdd(&s_xy[lb.w], ((u64)ay << 32) | ax);
        atomicAdd(&s_ij[lb.w], bi | ((u64)(j + 3) << 16));
    }
    __syncthreads();
    for (int q = t; q < K; q += 256) {
        u64 p = s_ij[q];
        if (p) {
            unsigned c = (unsigned)(p & 0xFFFFull);
            float sj = (float)(unsigned)((p >> 16) & 0xFFFFFFull);
            float si = (float)(unsigned)(p >> 40);
            u64 pxy = s_xy[q];
            long long ix = (long long)(unsigned)(pxy & 0xFFFFFFFFull) - (long long)c * 65536ll;
            long long iy = (long long)(unsigned)(pxy >> 32)           - (long long)c * 65536ll;
            red_v4(&g_sums[b * K + q], (float)ix * (1.f / 4096.f),
                   (float)iy * (1.f / 4096.f), si, sj);
            red_f(&g_cnt[b * K + q], (float)c);
        }
    }
}

// ---- pool fallback: direct global REDs ----
__global__ void pool_gl_k(const int*   __restrict__ labels,
                          const float* __restrict__ fxp,
                          const float* __restrict__ fyp,
                          int P, int h, int K, int Np) {
    int t = threadIdx.x;
    if (blockIdx.x == 0) {
        if (t < 20) g_xstat[t] = 0.f;
        if (t < 64) g_st2[t] = 0.f;
        if (t < 2)  g_bar[t] = 0u;
    }
    int p0 = blockIdx.x * blockDim.x + t;
    if (p0 >= Np) return;
    int b   = p0 / P;
    int pin = p0 - b * P;
    int i   = pin / h;
    int j   = pin - i * h;
    int l   = labels[p0];
    red_v4(&g_sums[b * K + l], fxp[p0], fyp[p0], (float)i, (float)j);
    red_f(&g_cnt[b * K + l], 1.f);
}

// ---- fused MLP: stats -> bar -> BN1-fold + layer1+layer2 -> bar -> BN2+norm+out
//      -> re-zero g_sums/g_cnt for next replay.  256 CTAs x 128 threads (co-resident).
__global__ void __launch_bounds__(128) mlp_all_k(
        const int*   __restrict__ fidx,
        const int*   __restrict__ nfp,
        const float* __restrict__ cw,   // [64,5]
        const float* __restrict__ cbp,  // [64]
        const float* __restrict__ g1,
        const float* __restrict__ b1,
        const float* __restrict__ lw,   // [32,64]
        const float* __restrict__ lbp,  // [32]
        const float* __restrict__ g2,
        const float* __restrict__ b2,
        float* __restrict__ out,
        int K, int BK, float sx, float sy, float invN) {
    __shared__ float xs[20];
    __shared__ float cw2p[512];
    __shared__ float wsm[2048];
    __shared__ float lbs[32];
    __shared__ float ssum[32], ssq[32];
    __shared__ float tile[4 * 528];
    __shared__ float sc2[32], sh2[32];

    int t = threadIdx.x, lane = t & 31, w = t >> 5;
    unsigned nCTA = gridDim.x;

    for (int q = t; q < 2048; q += 128) wsm[q] = __ldg(&lw[q]);
    if (t < 32) { lbs[t] = __ldg(&lbp[t]); ssum[t] = 0.f; ssq[t] = 0.f; }

    // ---- phase A: per-token features + Sx/Sxx stats ----
    {
        int nf = nfp ? *nfp : 100;
        float invnf = 1.f / (float)(nf - 1);
        float v[20];
#pragma unroll
        for (int q = 0; q < 20; q++) v[q] = 0.f;
        for (int tok = blockIdx.x * 128 + t; tok < BK; tok += nCTA * 128) {
            int b = tok / K;
            float x0 = (float)__ldg(&fidx[b]) * invnf;
            float cr = g_cnt[tok];
            float ic = 1.f / fmaxf(cr, 1.f);
            float4 s = g_sums[tok];
            float x1 = s.x * ic, x2 = s.y * ic;
            float x3 = (cr > 0.f) ? fmaf(s.z * ic, sx, -1.f) : 0.f;
            float x4 = (cr > 0.f) ? fmaf(s.w * ic, sy, -1.f) : 0.f;
            g_x[tok]          = x0;
            g_x[BK + tok]     = x1;
            g_x[2 * BK + tok] = x2;
            g_x[3 * BK + tok] = x3;
            g_x[4 * BK + tok] = x4;
            float xv[5] = {x0, x1, x2, x3, x4};
            int ix = 0;
#pragma unroll
            for (int d = 0; d < 5; d++) v[ix++] += xv[d];
#pragma unroll
            for (int d = 0; d < 5; d++)
#pragma unroll
                for (int e = d; e < 5; e++) v[ix++] += xv[d] * xv[e];
        }
#pragma unroll
        for (int q = 0; q < 20; q++) {
#pragma unroll
            for (int off = 16; off; off >>= 1)
                v[q] += __shfl_xor_sync(0xffffffffu, v[q], off);
        }
        if (lane == 0) {
#pragma unroll
            for (int q = 0; q < 20; q++) red_f(&g_xstat[q], v[q]);
        }
    }
    grid_barrier(0, nCTA);

    // ---- BN1 analytic fold ----
    if (t < 20) xs[t] = g_xstat[t];
    __syncthreads();
    if (t < 64) {
        int ch = t;
        float wv[5];
#pragma unroll
        for (int d = 0; d < 5; d++) wv[d] = __ldg(&cw[ch * 5 + d]);
        float bv = __ldg(&cbp[ch]);
        float m0 = 0.f;
#pragma unroll
        for (int d = 0; d < 5; d++) m0 = fmaf(wv[d], xs[d] * invN, m0);
        float q2 = 0.f; int ix = 5;
#pragma unroll
        for (int d = 0; d < 5; d++)
#pragma unroll
            for (int e = d; e < 5; e++) {
                float S = xs[ix++] * invN;
                q2 = fmaf((d == e ? 1.f : 2.f) * wv[d] * wv[e], S, q2);
            }
        float var = q2 - m0 * m0;
        float sc  = __ldg(&g1[ch]) * rsqrtf(var + EPS);
        float cbf = fmaf(bv, sc, __ldg(&b1[ch]) - (m0 + bv) * sc);
#pragma unroll
        for (int d = 0; d < 5; d++) cw2p[ch * 8 + d] = wv[d] * sc;
        cw2p[ch * 8 + 5] = cbf;
        cw2p[ch * 8 + 6] = 0.f;
        cw2p[ch * 8 + 7] = 0.f;
    }
    __syncthreads();

    // ---- phase B: layer1+layer2, thread = (token, half) [round-7 exact] ----
    float s1acc = 0.f, s2acc = 0.f;
    const float4* cw4 = (const float4*)cw2p;
    const float4* w4  = (const float4*)wsm;
    for (int tokbase = blockIdx.x * 64; tokbase < BK; tokbase += nCTA * 64) {
        int tok = tokbase + (t >> 1);
        int hf  = t & 1;
        bool act = tok < BK;
        int tclamp = act ? tok : (BK - 1);
        float x0 = g_x[tclamp];
        float x1 = g_x[BK + tclamp];
        float x2 = g_x[2 * BK + tclamp];
        float x3 = g_x[3 * BK + tclamp];
        float x4 = g_x[4 * BK + tclamp];

        float o[16];
#pragma unroll
        for (int c = 0; c < 16; c++) o[c] = lbs[hf * 16 + c];
#pragma unroll
        for (int chunk = 0; chunk < 4; chunk++) {
            float z[16];
#pragma unroll
            for (int c = 0; c < 16; c++) {
                int ch = chunk * 16 + c;
                float4 a = cw4[ch * 2];
                float4 b = cw4[ch * 2 + 1];
                float vv = fmaf(a.x, x0, fmaf(a.y, x1, fmaf(a.z, x2,
                           fmaf(a.w, x3, fmaf(b.x, x4, b.y)))));
                z[c] = fmaxf(vv, 0.f);
            }
#pragma unroll
            for (int cc = 0; cc < 16; cc++) {
                int row = (hf * 16 + cc) * 16 + chunk * 4;
#pragma unroll
                for (int q = 0; q < 4; q++) {
                    float4 ww = w4[row + q];
                    o[cc] = fmaf(z[q*4+0], ww.x, fmaf(z[q*4+1], ww.y,
                            fmaf(z[q*4+2], ww.z, fmaf(z[q*4+3], ww.w, o[cc]))));
                }
            }
        }
        if (!act) {
#pragma unroll
            for (int c = 0; c < 16; c++) o[c] = 0.f;
        }
        if (act) {
            float4* dst = (float4*)&g_t2[(size_t)tok * 32 + hf * 16];
#pragma unroll
            for (int q = 0; q < 4; q++)
                dst[q] = make_float4(o[4*q], o[4*q+1], o[4*q+2], o[4*q+3]);
        }
        // BN2 stats: per-warp stride-33 transpose
        float* tw = tile + w * 528;
        int tokin = (t >> 1) & 15;
        __syncwarp();
#pragma unroll
        for (int c = 0; c < 16; c++)
            tw[tokin * 33 + hf * 16 + c] = o[c];
        __syncwarp();
#pragma unroll
        for (int i = 0; i < 16; i++) {
            float vv = tw[i * 33 + lane];
            s1acc += vv; s2acc = fmaf(vv, vv, s2acc);
        }
    }
    atomicAdd(&ssum[lane], s1acc);
    atomicAdd(&ssq[lane], s2acc);
    __syncthreads();
    if (t < 32) { red_f(&g_st2[t], ssum[t]); red_f(&g_st2[32 + t], ssq[t]); }

    grid_barrier(1, nCTA);

    // ---- phase C: BN2 + ReLU + L2 normalize + write ----
    if (t < 32) {
        float m   = g_st2[t] * invN;
        float var = g_st2[32 + t] * invN - m * m;
        float s   = g2[t] * rsqrtf(var + EPS);
        sc2[t] = s; sh2[t] = b2[t] - m * s;
    }
    __syncthreads();
    float scl = sc2[lane], shl = sh2[lane];
    for (int tok0 = (blockIdx.x * 4 + w) * 8; tok0 < BK; tok0 += nCTA * 32) {
        float v[8];
#pragma unroll
        for (int tt = 0; tt < 8; tt++) {
            int tok = tok0 + tt;
            v[tt] = (tok < BK) ? g_t2[(size_t)tok * 32 + lane] : 0.f;
        }
#pragma unroll
        for (int tt = 0; tt < 8; tt++) {
            float x = fmaxf(fmaf(v[tt], scl, shl), 0.f);
            float n = x * x;
#pragma unroll
            for (int off = 16; off; off >>= 1)
                n += __shfl_xor_sync(0xffffffffu, n, off);
            float inv = 1.f / fmaxf(sqrtf(n), 1e-8f);
            int tok = tok0 + tt;
            if (tok < BK) out[(size_t)tok * 32 + lane] = x * inv;
        }
    }

    // ---- phase D: re-zero pool accumulators for next graph replay ----
    // Safe: all CTAs finished reading g_sums/g_cnt in phase A (ordered by bar 0/1).
    for (int i = blockIdx.x * 128 + t; i < BK; i += nCTA * 128) {
        g_sums[i] = make_float4(0.f, 0.f, 0.f, 0.f);
        g_cnt[i]  = 0.f;
    }
}

extern "C" void kernel_launch(void* const* d_in, const int* in_sizes, int n_in,
                              void* d_out, int out_size) {
    const int*   labels = (const int*)  d_in[0];
    const float* fx     = (const float*)d_in[1];
    const float* fy     = (const float*)d_in[2];
    const int*   fidx   = (const int*)  d_in[3];
    int wi = 4;
    const int* nfp = nullptr;
    if (n_in >= 14) { nfp = (const int*)d_in[4]; wi = 6; }
    const float* cw = (const float*)d_in[wi + 0];
    const float* cb = (const float*)d_in[wi + 1];
    const float* g1 = (const float*)d_in[wi + 2];
    const float* b1 = (const float*)d_in[wi + 3];
    const float* lw = (const float*)d_in[wi + 4];
    const float* lb = (const float*)d_in[wi + 5];
    const float* g2 = (const float*)d_in[wi + 6];
    const float* b2 = (const float*)d_in[wi + 7];

    int B  = in_sizes[3];
    int Np = in_sizes[0];
    int P  = Np / B;
    int BK = out_size / 32;
    int K  = BK / B;
    int hh = (int)(sqrt((double)P) + 0.5);
    int ww = P / hh;
    float sx = 2.f / (float)(ww - 1);
    float sy = 2.f / (float)(hh - 1);

    bool fast = (hh * ww == P) && (hh % 4 == 0) && (P % 4096 == 0) &&
                (K <= 2048) && (hh <= 1024) && (ww <= 1024);
    if (fast) {
        int cpb = P / 4096;
        pool_priv_k<<<B * cpb, 256, (size_t)K * 16>>>(labels, fx, fy, P, hh, K, cpb);
    } else {
        pool_gl_k<<<(Np + 255) / 256, 256>>>(labels, fx, fy, P, hh, K, Np);
    }

    float invN = 1.f / (float)BK;
    mlp_all_k<<<256, 128>>>(fidx, nfp, cw, cb, g1, b1, lw, lb, g2, b2,
                            (float*)d_out, K, BK, sx, sy, invN);
}